// round 2
// baseline (speedup 1.0000x reference)
#include <cuda_runtime.h>

#define N_NODESC 50000
#define N_EDGESC 400000

// ---------------- device scratch (static, no runtime alloc) ----------------
__device__ float g_AB[(size_t)N_NODESC * 512];      // [n][0:256]=A(+b_edge), [n][256:512]=B
__device__ float g_nodeagg[(size_t)N_NODESC * 128];
__device__ float g_edgeagg[(size_t)N_NODESC * 256];
__device__ float g_nodes[(size_t)N_NODESC * 256];
__device__ float g_edges[(size_t)N_NODESC * 128];
__device__ float g_Wc[128 * 512];
__device__ float g_bc[512];
__device__ int   g_count[N_NODESC];
__device__ int   g_off[N_NODESC + 1];
__device__ int   g_cur[N_NODESC];
__device__ int   g_csr[N_EDGESC];
__device__ int   g_ei32[2 * N_EDGESC];   // converted indices (int32)
__device__ int   g_dtype_flag;           // nonzero -> input buffer is int32

// ---------------- packed f32x2 helpers (sm_103a FFMA2 path) ----------------
__device__ __forceinline__ unsigned long long pack2(float x, float y) {
    unsigned long long r;
    asm("mov.b64 %0, {%1, %2};" : "=l"(r) : "f"(x), "f"(y));
    return r;
}
__device__ __forceinline__ void fma2(unsigned long long& d, unsigned long long a, unsigned long long b) {
    asm("fma.rn.f32x2 %0, %1, %2, %3;" : "=l"(d) : "l"(a), "l"(b), "l"(d));
}
__device__ __forceinline__ float2 unpack2(unsigned long long v) {
    float2 r;
    asm("mov.b64 {%0, %1}, %2;" : "=f"(r.x), "=f"(r.y) : "l"(v));
    return r;
}

// ---------------- dtype detect + convert (int32 vs int64 edge_index) ----------------
__global__ void zero_init_kernel() {
    int i = blockIdx.x * blockDim.x + threadIdx.x;
    if (i < N_NODESC) g_count[i] = 0;
    if (i == 0) g_dtype_flag = 0;
}

// OR-reduce odd 32-bit words of the first 2*N_EDGES words. For an int64 buffer
// of values < 50000, the high halves (odd words) are all zero -> flag stays 0.
// For an int32 buffer, odd words are random dst indices -> flag becomes nonzero.
__global__ void detect_kernel(const int* __restrict__ w) {
    int acc = 0;
    for (int i = blockIdx.x * blockDim.x + threadIdx.x; i < N_EDGESC; i += gridDim.x * blockDim.x)
        acc |= w[2 * i + 1];
    #pragma unroll
    for (int o = 16; o; o >>= 1) acc |= __shfl_xor_sync(0xffffffffu, acc, o);
    if ((threadIdx.x & 31) == 0 && acc) atomicOr(&g_dtype_flag, 1);
}

__global__ void convert_kernel(const void* __restrict__ ei) {
    int e = blockIdx.x * blockDim.x + threadIdx.x;
    if (e < 2 * N_EDGESC) {
        int v;
        if (g_dtype_flag) v = ((const int*)ei)[e];
        else              v = (int)((const long long*)ei)[e];
        g_ei32[e] = v;
    }
}

// ---------------- CSR build ----------------
__global__ void hist_kernel() {
    int e = blockIdx.x * blockDim.x + threadIdx.x;
    if (e < N_EDGESC) atomicAdd(&g_count[g_ei32[N_EDGESC + e]], 1);
}

__global__ void scan_kernel() {
    __shared__ int wsum[33];
    __shared__ int carry;
    int tid = threadIdx.x, lane = tid & 31, w = tid >> 5;
    if (tid == 0) carry = 0;
    __syncthreads();
    for (int base = 0; base < N_NODESC; base += 1024) {
        int i = base + tid;
        int orig = (i < N_NODESC) ? g_count[i] : 0;
        int v = orig;
        #pragma unroll
        for (int o = 1; o < 32; o <<= 1) {
            int t = __shfl_up_sync(0xffffffffu, v, o);
            if (lane >= o) v += t;
        }
        if (lane == 31) wsum[w] = v;
        __syncthreads();
        if (w == 0) {
            int s = wsum[lane], sv = s;
            #pragma unroll
            for (int o = 1; o < 32; o <<= 1) {
                int t = __shfl_up_sync(0xffffffffu, sv, o);
                if (lane >= o) sv += t;
            }
            wsum[lane] = sv - s;
            if (lane == 31) wsum[32] = sv;
        }
        __syncthreads();
        if (i < N_NODESC) {
            int ex = carry + wsum[w] + v - orig;   // exclusive prefix
            g_off[i] = ex;
            g_cur[i] = ex;
        }
        __syncthreads();
        if (tid == 0) carry += wsum[32];
        __syncthreads();
    }
    if (tid == 0) g_off[N_NODESC] = carry;
}

__global__ void scatter_kernel() {
    int e = blockIdx.x * blockDim.x + threadIdx.x;
    if (e < N_EDGESC) {
        int d = g_ei32[N_EDGESC + e];
        int s = g_ei32[e];
        int p = atomicAdd(&g_cur[d], 1);
        g_csr[p] = s;
    }
}

// ---------------- weight prep: Wc = [W_top - W_bot | W_bot], bc = [b_edge | 0] ----------------
__global__ void prep_kernel(const float* __restrict__ We, const float* __restrict__ be) {
    int idx = blockIdx.x * blockDim.x + threadIdx.x;
    if (idx < 128 * 512) {
        int k = idx >> 9, j = idx & 511;
        float v;
        if (j < 256) v = We[k * 256 + j] - We[(128 + k) * 256 + j];
        else         v = We[(128 + k) * 256 + (j - 256)];
        g_Wc[idx] = v;
    }
    if (idx < 512) g_bc[idx] = (idx < 256) ? be[idx] : 0.0f;
}

// ---------------- fp32 tiled GEMM with packed FFMA2: out[M,N] = act(A[M,K] @ W[K,N] + bias) ----------------
template <int K, bool RELU>
__global__ __launch_bounds__(256) void gemm_kernel(
    const float* __restrict__ A, const float* __restrict__ W,
    const float* __restrict__ bias, float* __restrict__ out,
    int M, int Nfull)
{
    const int TM = 64, TN = 128, KC = 32;
    __shared__ __align__(16) float As[KC][TM + 4];
    __shared__ __align__(16) float Ws[KC][TN + 4];
    int tid = threadIdx.x;
    int tx = tid & 15, ty = tid >> 4;   // 16 col-groups x 16 row-groups
    int m0 = blockIdx.y * TM, n0 = blockIdx.x * TN;

    unsigned long long acc[4][4];
    unsigned long long z = pack2(0.0f, 0.0f);
    #pragma unroll
    for (int r = 0; r < 4; r++)
        #pragma unroll
        for (int c = 0; c < 4; c++) acc[r][c] = z;

    for (int k0 = 0; k0 < K; k0 += KC) {
        #pragma unroll
        for (int j = 0; j < 8; j++) {                 // 64x32 A tile
            int idx = tid + j * 256;
            int m = idx >> 5, kk = idx & 31;
            int row = m0 + m;
            As[kk][m] = (row < M) ? A[(size_t)row * K + k0 + kk] : 0.0f;
        }
        #pragma unroll
        for (int j = 0; j < 16; j++) {                // 32x128 W tile
            int idx = tid + j * 256;
            int kk = idx >> 7, n = idx & 127;
            Ws[kk][n] = W[(size_t)(k0 + kk) * Nfull + n0 + n];
        }
        __syncthreads();
        #pragma unroll
        for (int kk = 0; kk < KC; kk++) {
            float4 av = *(const float4*)&As[kk][ty * 4];
            unsigned long long a0 = pack2(av.x, av.x);
            unsigned long long a1 = pack2(av.y, av.y);
            unsigned long long a2 = pack2(av.z, av.z);
            unsigned long long a3 = pack2(av.w, av.w);
            const unsigned long long* wr = (const unsigned long long*)&Ws[kk][0];
            unsigned long long b0 = wr[tx * 4 + 0];
            unsigned long long b1 = wr[tx * 4 + 1];
            unsigned long long b2 = wr[tx * 4 + 2];
            unsigned long long b3 = wr[tx * 4 + 3];
            fma2(acc[0][0], a0, b0); fma2(acc[0][1], a0, b1); fma2(acc[0][2], a0, b2); fma2(acc[0][3], a0, b3);
            fma2(acc[1][0], a1, b0); fma2(acc[1][1], a1, b1); fma2(acc[1][2], a1, b2); fma2(acc[1][3], a1, b3);
            fma2(acc[2][0], a2, b0); fma2(acc[2][1], a2, b1); fma2(acc[2][2], a2, b2); fma2(acc[2][3], a2, b3);
            fma2(acc[3][0], a3, b0); fma2(acc[3][1], a3, b1); fma2(acc[3][2], a3, b2); fma2(acc[3][3], a3, b3);
        }
        __syncthreads();
    }

    int col0 = n0 + tx * 8;
    float bv[8];
    #pragma unroll
    for (int c = 0; c < 8; c++) bv[c] = bias[col0 + c];
    #pragma unroll
    for (int r = 0; r < 4; r++) {
        int row = m0 + ty * 4 + r;
        if (row >= M) continue;
        float o[8];
        #pragma unroll
        for (int c = 0; c < 4; c++) {
            float2 u = unpack2(acc[r][c]);
            o[2 * c] = u.x; o[2 * c + 1] = u.y;
        }
        #pragma unroll
        for (int c = 0; c < 8; c++) {
            float v = o[c] + bv[c];
            if (RELU) v = fmaxf(v, 0.0f);
            o[c] = v;
        }
        float4* op = (float4*)(out + (size_t)row * Nfull + col0);
        op[0] = make_float4(o[0], o[1], o[2], o[3]);
        op[1] = make_float4(o[4], o[5], o[6], o[7]);
    }
}

// ---------------- per-dst-node aggregation: node_agg = sum x[src], edge_agg = sum relu(A[dst]+B[src]) ----------------
__global__ void aggregate_kernel(const float* __restrict__ x) {
    int gw = (blockIdx.x * blockDim.x + threadIdx.x) >> 5;
    int lane = threadIdx.x & 31;
    if (gw >= N_NODESC) return;
    int beg = g_off[gw], end = g_off[gw + 1];
    const float4* Ar = (const float4*)(g_AB + (size_t)gw * 512);
    float4 a0 = Ar[lane], a1 = Ar[32 + lane];   // A row (bias folded in)
    float4 na = make_float4(0, 0, 0, 0);
    float4 e0 = na, e1 = na;
    for (int e = beg; e < end; e++) {
        int s = g_csr[e];
        const float4* xr = (const float4*)(x + (size_t)s * 128);
        const float4* br = (const float4*)(g_AB + (size_t)s * 512);
        float4 xv = xr[lane];
        float4 b0 = br[64 + lane], b1 = br[96 + lane];
        na.x += xv.x; na.y += xv.y; na.z += xv.z; na.w += xv.w;
        e0.x += fmaxf(a0.x + b0.x, 0.0f);
        e0.y += fmaxf(a0.y + b0.y, 0.0f);
        e0.z += fmaxf(a0.z + b0.z, 0.0f);
        e0.w += fmaxf(a0.w + b0.w, 0.0f);
        e1.x += fmaxf(a1.x + b1.x, 0.0f);
        e1.y += fmaxf(a1.y + b1.y, 0.0f);
        e1.z += fmaxf(a1.z + b1.z, 0.0f);
        e1.w += fmaxf(a1.w + b1.w, 0.0f);
    }
    ((float4*)(g_nodeagg + (size_t)gw * 128))[lane] = na;
    float4* er = (float4*)(g_edgeagg + (size_t)gw * 256);
    er[lane] = e0;
    er[32 + lane] = e1;
}

// ---------------- fused head: h = relu([nodes|edges]@W_f1+b1); out = sigmoid(h@W_f2+b2) ----------------
__global__ void fuse_kernel(const float* __restrict__ Wf1, const float* __restrict__ bf1,
                            const float* __restrict__ Wf2, const float* __restrict__ bf2,
                            float* __restrict__ out) {
    int gw = (blockIdx.x * blockDim.x + threadIdx.x) >> 5;
    int lane = threadIdx.x & 31;
    if (gw >= N_NODESC) return;
    const float* nr = g_nodes + (size_t)gw * 256;
    const float* er = g_edges + (size_t)gw * 128;
    float h = bf1[lane];
    #pragma unroll 8
    for (int k = 0; k < 256; k++) h = fmaf(nr[k], Wf1[k * 32 + lane], h);
    #pragma unroll 8
    for (int k = 0; k < 128; k++) h = fmaf(er[k], Wf1[(256 + k) * 32 + lane], h);
    h = fmaxf(h, 0.0f);
    float t = h * Wf2[lane];
    #pragma unroll
    for (int o = 16; o; o >>= 1) t += __shfl_xor_sync(0xffffffffu, t, o);
    if (lane == 0) out[gw] = 1.0f / (1.0f + __expf(-(t + bf2[0])));
}

// ---------------- launch ----------------
extern "C" void kernel_launch(void* const* d_in, const int* in_sizes, int n_in,
                              void* d_out, int out_size) {
    const float* x  = (const float*)d_in[0];
    const void*  ei = d_in[1];               // int32 or int64, detected on device
    // d_in[2] = e (unused by the math)
    const float* W_node = (const float*)d_in[3];
    const float* b_node = (const float*)d_in[4];
    const float* W_edge = (const float*)d_in[5];
    const float* b_edge = (const float*)d_in[6];
    const float* W_ed   = (const float*)d_in[7];
    const float* b_ed   = (const float*)d_in[8];
    const float* W_f1   = (const float*)d_in[9];
    const float* b_f1   = (const float*)d_in[10];
    const float* W_f2   = (const float*)d_in[11];
    const float* b_f2   = (const float*)d_in[12];
    float* out = (float*)d_out;

    // Resolve device-global scratch addresses (query only; capture-safe, no allocation)
    float *pAB, *pWc, *pbc, *pna, *pea, *pnodes, *pedges;
    cudaGetSymbolAddress((void**)&pAB, g_AB);
    cudaGetSymbolAddress((void**)&pWc, g_Wc);
    cudaGetSymbolAddress((void**)&pbc, g_bc);
    cudaGetSymbolAddress((void**)&pna, g_nodeagg);
    cudaGetSymbolAddress((void**)&pea, g_edgeagg);
    cudaGetSymbolAddress((void**)&pnodes, g_nodes);
    cudaGetSymbolAddress((void**)&pedges, g_edges);

    // dtype detect + convert indices to int32
    zero_init_kernel<<<(N_NODESC + 255) / 256, 256>>>();
    detect_kernel<<<256, 256>>>((const int*)ei);
    convert_kernel<<<(2 * N_EDGESC + 255) / 256, 256>>>(ei);

    // CSR build
    hist_kernel<<<(N_EDGESC + 255) / 256, 256>>>();
    scan_kernel<<<1, 1024>>>();
    scatter_kernel<<<(N_EDGESC + 255) / 256, 256>>>();

    // Weight prep + AB = x @ Wc (A has b_edge folded in)
    prep_kernel<<<(128 * 512 + 255) / 256, 256>>>(W_edge, b_edge);
    gemm_kernel<128, false><<<dim3(4, (N_NODESC + 63) / 64), 256>>>(x, pWc, pbc, pAB, N_NODESC, 512);

    // Per-node aggregation over CSR (no atomics)
    aggregate_kernel<<<(N_NODESC + 7) / 8, 256>>>(x);

    // Node / edge dense layers
    gemm_kernel<128, true><<<dim3(2, (N_NODESC + 63) / 64), 256>>>(pna, W_node, b_node, pnodes, N_NODESC, 256);
    gemm_kernel<256, true><<<dim3(1, (N_NODESC + 63) / 64), 256>>>(pea, W_ed, b_ed, pedges, N_NODESC, 128);

    // Fused head
    fuse_kernel<<<(N_NODESC + 7) / 8, 256>>>(W_f1, b_f1, W_f2, b_f2, out);
}

// round 3
// speedup vs baseline: 1.9783x; 1.9783x over previous
#include <cuda_runtime.h>
#include <cuda_bf16.h>

#define N_NODESC 50000
#define N_EDGESC 400000

// ---------------- device scratch (static, no runtime alloc) ----------------
__device__ float g_AB[(size_t)N_NODESC * 512];      // [n][0:256]=A(+b_edge), [n][256:512]=B
__device__ float g_nodeagg[(size_t)N_NODESC * 128];
__device__ float g_edgeagg[(size_t)N_NODESC * 256];
__device__ float g_h[(size_t)N_NODESC * 384];       // [nodes(256) | edges(128)]
__device__ float g_h2[(size_t)N_NODESC * 32];
__device__ float g_Wc[128 * 512];
__device__ float g_bc[512];
__device__ int   g_count[N_NODESC];
__device__ int   g_off[N_NODESC + 1];
__device__ int   g_cur[N_NODESC];
__device__ int   g_csr[N_EDGESC];
__device__ int   g_ei32[2 * N_EDGESC];
__device__ int   g_dtype_flag;

// ---------------- dtype detect + convert (int32 vs int64 edge_index) ----------------
__global__ void zero_init_kernel() {
    int i = blockIdx.x * blockDim.x + threadIdx.x;
    if (i < N_NODESC) g_count[i] = 0;
    if (i == 0) g_dtype_flag = 0;
}

__global__ void detect_kernel(const int* __restrict__ w) {
    int acc = 0;
    for (int i = blockIdx.x * blockDim.x + threadIdx.x; i < N_EDGESC; i += gridDim.x * blockDim.x)
        acc |= w[2 * i + 1];
    #pragma unroll
    for (int o = 16; o; o >>= 1) acc |= __shfl_xor_sync(0xffffffffu, acc, o);
    if ((threadIdx.x & 31) == 0 && acc) atomicOr(&g_dtype_flag, 1);
}

__global__ void convert_kernel(const void* __restrict__ ei) {
    int e = blockIdx.x * blockDim.x + threadIdx.x;
    if (e < 2 * N_EDGESC) {
        int v;
        if (g_dtype_flag) v = ((const int*)ei)[e];
        else              v = (int)((const long long*)ei)[e];
        g_ei32[e] = v;
    }
}

// ---------------- CSR build ----------------
__global__ void hist_kernel() {
    int e = blockIdx.x * blockDim.x + threadIdx.x;
    if (e < N_EDGESC) atomicAdd(&g_count[g_ei32[N_EDGESC + e]], 1);
}

__global__ void scan_kernel() {
    __shared__ int wsum[33];
    __shared__ int carry;
    int tid = threadIdx.x, lane = tid & 31, w = tid >> 5;
    if (tid == 0) carry = 0;
    __syncthreads();
    for (int base = 0; base < N_NODESC; base += 1024) {
        int i = base + tid;
        int orig = (i < N_NODESC) ? g_count[i] : 0;
        int v = orig;
        #pragma unroll
        for (int o = 1; o < 32; o <<= 1) {
            int t = __shfl_up_sync(0xffffffffu, v, o);
            if (lane >= o) v += t;
        }
        if (lane == 31) wsum[w] = v;
        __syncthreads();
        if (w == 0) {
            int s = wsum[lane], sv = s;
            #pragma unroll
            for (int o = 1; o < 32; o <<= 1) {
                int t = __shfl_up_sync(0xffffffffu, sv, o);
                if (lane >= o) sv += t;
            }
            wsum[lane] = sv - s;
            if (lane == 31) wsum[32] = sv;
        }
        __syncthreads();
        if (i < N_NODESC) {
            int ex = carry + wsum[w] + v - orig;
            g_off[i] = ex;
            g_cur[i] = ex;
        }
        __syncthreads();
        if (tid == 0) carry += wsum[32];
        __syncthreads();
    }
    if (tid == 0) g_off[N_NODESC] = carry;
}

__global__ void scatter_kernel() {
    int e = blockIdx.x * blockDim.x + threadIdx.x;
    if (e < N_EDGESC) {
        int d = g_ei32[N_EDGESC + e];
        int s = g_ei32[e];
        int p = atomicAdd(&g_cur[d], 1);
        g_csr[p] = s;
    }
}

// ---------------- weight prep: Wc = [W_top - W_bot | W_bot], bc = [b_edge | 0] ----------------
__global__ void prep_kernel(const float* __restrict__ We, const float* __restrict__ be) {
    int idx = blockIdx.x * blockDim.x + threadIdx.x;
    if (idx < 128 * 512) {
        int k = idx >> 9, j = idx & 511;
        float v;
        if (j < 256) v = We[k * 256 + j] - We[(128 + k) * 256 + j];
        else         v = We[(128 + k) * 256 + (j - 256)];
        g_Wc[idx] = v;
    }
    if (idx < 512) g_bc[idx] = (idx < 256) ? be[idx] : 0.0f;
}

// ---------------- bf16-split tensor-core GEMM ----------------
// out[M,N] = act(A[M,K] @ W[K,N] + bias) with A,W split as hi+lo bf16
// (3 mma passes: hi*hi + hi*lo + lo*hi -> ~2^-16 product error)
__device__ __forceinline__ void mma16816(float* d, const unsigned* a, const unsigned* b) {
    asm volatile(
        "mma.sync.aligned.m16n8k16.row.col.f32.bf16.bf16.f32 "
        "{%0,%1,%2,%3}, {%4,%5,%6,%7}, {%8,%9}, {%0,%1,%2,%3};\n"
        : "+f"(d[0]), "+f"(d[1]), "+f"(d[2]), "+f"(d[3])
        : "r"(a[0]), "r"(a[1]), "r"(a[2]), "r"(a[3]), "r"(b[0]), "r"(b[1]));
}

__device__ __forceinline__ void split_bf16x2(float2 v, unsigned& hi, unsigned& lo) {
    __nv_bfloat162 h = __float22bfloat162_rn(v);
    float2 hf = __bfloat1622float2(h);
    __nv_bfloat162 l = __float22bfloat162_rn(make_float2(v.x - hf.x, v.y - hf.y));
    hi = *(unsigned*)&h;
    lo = *(unsigned*)&l;
}

template <int BM, int BN, int WM, int WN, bool RELU>
__global__ __launch_bounds__(256) void mma_gemm(
    const float* __restrict__ A, int lda,
    const float* __restrict__ W, int ldw,
    const float* __restrict__ bias,
    float* __restrict__ out, int ldo, int ocol0,
    int M, int K)
{
    constexpr int KC = 16;             // one k16 step per stage
    constexpr int WARPS_N = BN / WN;
    constexpr int MT = WM / 16, NT = WN / 8;
    // row stride 12 words -> conflict-free fragment LDS (gcd analysis)
    __shared__ unsigned Ah[BM][12], Al[BM][12];
    __shared__ unsigned Wh[BN][12], Wl[BN][12];

    int tid = threadIdx.x;
    int w = tid >> 5, lane = tid & 31;
    int gr = lane >> 2, thc = lane & 3;
    int wm = w / WARPS_N, wn = w % WARPS_N;
    int m0 = blockIdx.y * BM, n0 = blockIdx.x * BN;
    int m0w = wm * WM, n0w = wn * WN;

    float d[MT][NT][4];
    #pragma unroll
    for (int i = 0; i < MT; i++)
        #pragma unroll
        for (int j = 0; j < NT; j++)
            #pragma unroll
            for (int q = 0; q < 4; q++) d[i][j][q] = 0.0f;

    for (int k0 = 0; k0 < K; k0 += KC) {
        // fill A tile (BM x 16 fp32 -> hi/lo bf16 pairs)
        #pragma unroll
        for (int j = 0; j < (BM * 8) / 256; j++) {
            int p = tid + j * 256;
            int row = p >> 3, c = p & 7;
            float2 v = make_float2(0.0f, 0.0f);
            if (m0 + row < M)
                v = *(const float2*)(A + (size_t)(m0 + row) * lda + k0 + 2 * c);
            split_bf16x2(v, Ah[row][c], Al[row][c]);
        }
        // fill W tile transposed: Wh[n][kpair]
        #pragma unroll
        for (int j = 0; j < (BN * 8 + 255) / 256; j++) {
            int e = tid + j * 256;
            if (e < BN * 8) {
                int n = e % BN, c = e / BN;
                float2 v = make_float2(W[(size_t)(k0 + 2 * c) * ldw + n0 + n],
                                       W[(size_t)(k0 + 2 * c + 1) * ldw + n0 + n]);
                split_bf16x2(v, Wh[n][c], Wl[n][c]);
            }
        }
        __syncthreads();

        unsigned ah[MT][4], al[MT][4], bh[NT][2], bl[NT][2];
        #pragma unroll
        for (int i = 0; i < MT; i++) {
            int r0 = m0w + 16 * i + gr, r1 = r0 + 8;
            ah[i][0] = Ah[r0][thc];     ah[i][1] = Ah[r1][thc];
            ah[i][2] = Ah[r0][thc + 4]; ah[i][3] = Ah[r1][thc + 4];
            al[i][0] = Al[r0][thc];     al[i][1] = Al[r1][thc];
            al[i][2] = Al[r0][thc + 4]; al[i][3] = Al[r1][thc + 4];
        }
        #pragma unroll
        for (int j = 0; j < NT; j++) {
            int nn = n0w + 8 * j + gr;
            bh[j][0] = Wh[nn][thc]; bh[j][1] = Wh[nn][thc + 4];
            bl[j][0] = Wl[nn][thc]; bl[j][1] = Wl[nn][thc + 4];
        }
        #pragma unroll
        for (int i = 0; i < MT; i++)
            #pragma unroll
            for (int j = 0; j < NT; j++) {
                mma16816(d[i][j], ah[i], bh[j]);
                mma16816(d[i][j], ah[i], bl[j]);
                mma16816(d[i][j], al[i], bh[j]);
            }
        __syncthreads();
    }

    // epilogue: bias + activation, float2 stores
    #pragma unroll
    for (int i = 0; i < MT; i++) {
        int row0 = m0 + m0w + 16 * i + gr;
        int row1 = row0 + 8;
        #pragma unroll
        for (int j = 0; j < NT; j++) {
            int col = n0 + n0w + 8 * j + 2 * thc;
            float b0 = bias[col], b1 = bias[col + 1];
            float v00 = d[i][j][0] + b0, v01 = d[i][j][1] + b1;
            float v10 = d[i][j][2] + b0, v11 = d[i][j][3] + b1;
            if (RELU) {
                v00 = fmaxf(v00, 0.0f); v01 = fmaxf(v01, 0.0f);
                v10 = fmaxf(v10, 0.0f); v11 = fmaxf(v11, 0.0f);
            }
            if (row0 < M) *(float2*)(out + (size_t)row0 * ldo + ocol0 + col) = make_float2(v00, v01);
            if (row1 < M) *(float2*)(out + (size_t)row1 * ldo + ocol0 + col) = make_float2(v10, v11);
        }
    }
}

// ---------------- per-dst-node aggregation ----------------
__global__ void aggregate_kernel(const float* __restrict__ x) {
    int gw = (blockIdx.x * blockDim.x + threadIdx.x) >> 5;
    int lane = threadIdx.x & 31;
    if (gw >= N_NODESC) return;
    int beg = g_off[gw], end = g_off[gw + 1];
    const float4* Ar = (const float4*)(g_AB + (size_t)gw * 512);
    float4 a0 = Ar[lane], a1 = Ar[32 + lane];
    float4 na = make_float4(0, 0, 0, 0);
    float4 e0 = na, e1 = na;
    for (int e = beg; e < end; e++) {
        int s = g_csr[e];
        const float4* xr = (const float4*)(x + (size_t)s * 128);
        const float4* br = (const float4*)(g_AB + (size_t)s * 512);
        float4 xv = xr[lane];
        float4 b0 = br[64 + lane], b1 = br[96 + lane];
        na.x += xv.x; na.y += xv.y; na.z += xv.z; na.w += xv.w;
        e0.x += fmaxf(a0.x + b0.x, 0.0f);
        e0.y += fmaxf(a0.y + b0.y, 0.0f);
        e0.z += fmaxf(a0.z + b0.z, 0.0f);
        e0.w += fmaxf(a0.w + b0.w, 0.0f);
        e1.x += fmaxf(a1.x + b1.x, 0.0f);
        e1.y += fmaxf(a1.y + b1.y, 0.0f);
        e1.z += fmaxf(a1.z + b1.z, 0.0f);
        e1.w += fmaxf(a1.w + b1.w, 0.0f);
    }
    ((float4*)(g_nodeagg + (size_t)gw * 128))[lane] = na;
    float4* er = (float4*)(g_edgeagg + (size_t)gw * 256);
    er[lane] = e0;
    er[32 + lane] = e1;
}

// ---------------- final: out = sigmoid(h2 @ W_f2 + b_f2) ----------------
__global__ void sigmoid_kernel(const float* __restrict__ Wf2, const float* __restrict__ bf2,
                               float* __restrict__ out) {
    int gw = (blockIdx.x * blockDim.x + threadIdx.x) >> 5;
    int lane = threadIdx.x & 31;
    if (gw >= N_NODESC) return;
    float t = g_h2[(size_t)gw * 32 + lane] * Wf2[lane];
    #pragma unroll
    for (int o = 16; o; o >>= 1) t += __shfl_xor_sync(0xffffffffu, t, o);
    if (lane == 0) out[gw] = 1.0f / (1.0f + __expf(-(t + bf2[0])));
}

// ---------------- launch ----------------
extern "C" void kernel_launch(void* const* d_in, const int* in_sizes, int n_in,
                              void* d_out, int out_size) {
    const float* x  = (const float*)d_in[0];
    const void*  ei = d_in[1];
    const float* W_node = (const float*)d_in[3];
    const float* b_node = (const float*)d_in[4];
    const float* W_edge = (const float*)d_in[5];
    const float* b_edge = (const float*)d_in[6];
    const float* W_ed   = (const float*)d_in[7];
    const float* b_ed   = (const float*)d_in[8];
    const float* W_f1   = (const float*)d_in[9];
    const float* b_f1   = (const float*)d_in[10];
    const float* W_f2   = (const float*)d_in[11];
    const float* b_f2   = (const float*)d_in[12];
    float* out = (float*)d_out;

    float *pAB, *pWc, *pbc, *pna, *pea, *ph, *ph2;
    cudaGetSymbolAddress((void**)&pAB, g_AB);
    cudaGetSymbolAddress((void**)&pWc, g_Wc);
    cudaGetSymbolAddress((void**)&pbc, g_bc);
    cudaGetSymbolAddress((void**)&pna, g_nodeagg);
    cudaGetSymbolAddress((void**)&pea, g_edgeagg);
    cudaGetSymbolAddress((void**)&ph,  g_h);
    cudaGetSymbolAddress((void**)&ph2, g_h2);

    const int MB = (N_NODESC + 127) / 128;   // 391

    // dtype detect + convert indices to int32
    zero_init_kernel<<<(N_NODESC + 255) / 256, 256>>>();
    detect_kernel<<<256, 256>>>((const int*)ei);
    convert_kernel<<<(2 * N_EDGESC + 255) / 256, 256>>>(ei);

    // CSR build
    hist_kernel<<<(N_EDGESC + 255) / 256, 256>>>();
    scan_kernel<<<1, 1024>>>();
    scatter_kernel<<<(N_EDGESC + 255) / 256, 256>>>();

    // Weight prep + AB = x @ Wc (b_edge folded into A-half bias)
    prep_kernel<<<(128 * 512 + 255) / 256, 256>>>(W_edge, b_edge);
    mma_gemm<128, 64, 32, 32, false><<<dim3(8, MB), 256>>>(x, 128, pWc, 512, pbc, pAB, 512, 0, N_NODESC, 128);

    // Per-node aggregation over CSR (no atomics)
    aggregate_kernel<<<(N_NODESC + 7) / 8, 256>>>(x);

    // Node / edge dense layers -> concatenated into g_h
    mma_gemm<128, 64, 32, 32, true><<<dim3(4, MB), 256>>>(pna, 128, W_node, 256, b_node, ph, 384, 0,   N_NODESC, 128);
    mma_gemm<128, 64, 32, 32, true><<<dim3(2, MB), 256>>>(pea, 256, W_ed,   128, b_ed,   ph, 384, 256, N_NODESC, 256);

    // Fuse layer 1 as GEMM: h2 = relu(g_h @ W_f1 + b_f1)
    mma_gemm<128, 32, 32, 16, true><<<dim3(1, MB), 256>>>(ph, 384, W_f1, 32, b_f1, ph2, 32, 0, N_NODESC, 384);

    // Final dot + sigmoid
    sigmoid_kernel<<<(N_NODESC + 7) / 8, 256>>>(W_f2, b_f2, out);
}